// round 16
// baseline (speedup 1.0000x reference)
#include <cuda_runtime.h>
#include <math.h>

// Problem constants (from reference)
#define MAXN   524288
#define SPIN   1000
#define TRAINN 400000
#define ML_C   2.9086f
#define SL_C   1.898f

#define L_C    32                 // core steps per chunk (lane)
#define WARM   48                 // speculative burn-in (contraction)
#define STEPS  (WARM + L_C)       // 80 sequential steps per lane
#define SPAN   (31*L_C + STEPS)   // 1072 unique elements per warp
#define SU_SZ  2168               // >= SWZ(SPAN)=2161 (+pad)
#define SWZ(o) ((o) + 33*((o) >> 5))
#define SSC_SZ (32*33)
#define WSTRIDE (3*SU_SZ + SSC_SZ)
#define SCAN_TPB 64
#define SCAN_BLOCKS 256
#define REDB2   64                // reduce blocks appended to the scan grid
#define TOT_BLOCKS (SCAN_BLOCKS + REDB2)
#define SCAN_SMEM (2*WSTRIDE*4)   // bytes (2 warps)

// Scratch (no allocations allowed)
__device__ float2   g_cu[MAXN];       // packed (c0, u2) per element
__device__ double   g_part[REDB2*2];  // per-block partial sums
__device__ unsigned g_ctr = 0;        // completion counter (self-resetting)
__device__ float    g_obs[1];         // obsstd result

// ---------------------------------------------------------------------------
struct Par {
    float A2, B2, oo1, noo1, svm, nsvm, mthr, K, AL, BL, ol1;
};

__device__ __forceinline__ Par make_par(
        const float* pm, const float* ps,
        const float* wr_yom, const float* wr_ylm,
        const float* wr_yfm, const float* wr_yvm,
        const float* b0_yom, const float* wb1p,
        const float* b0_ylm, const float* wb2p,
        const float* b0_yrm) {
    const float LOG2E = 1.4426950408889634f;
    Par p;
    float eo = expf(wr_yom[0]);
    float el = expf(wr_ylm[0]);
    float ef = expf(wr_yfm[0]);
    float den = eo + el + ef;
    p.oo1  = eo / den;
    p.ol1  = el / den;
    p.noo1 = -p.oo1;
    p.svm  = 1.0f / (1.0f + expf(-wr_yvm[0]));
    p.nsvm = -p.svm;
    float thr = expf(b0_yrm[0]);
    p.mthr = -thr;
    p.K    = thr * 500.0f;
    float a = wb1p[0] / ps[0];
    p.A2 = -LOG2E * a;
    p.B2 = -LOG2E * (b0_yom[0] - pm[0] * a);
    float al = wb2p[0] / SL_C;
    p.AL = -LOG2E * al;
    p.BL = -LOG2E * (b0_ylm[0] - ML_C * al);
    return p;
}

__device__ __forceinline__ float olgate(float u2, const Par& p) {
    float t = fmaf(u2, p.AL, p.BL);
    float e; asm("ex2.approx.f32 %0, %1;" : "=f"(e) : "f"(t));
    float r; asm("rcp.approx.f32 %0, %1;" : "=f"(r) : "f"(1.0f + e));
    return p.ol1 * r;
}

// One recurrence step (branch-free; all selects are FSELs). ol precomputed.
__device__ __forceinline__ float stepf(float c0, float u1, float u2, float ol,
                                       const Par& p) {
    float t = fmaf(c0, p.A2, p.B2);
    float e;  asm("ex2.approx.f32 %0, %1;" : "=f"(e) : "f"(t));
    float d = 1.0f + e;
    float r;  asm("rcp.approx.f32 %0, %1;" : "=f"(r) : "f"(d));
    float rc; asm("rcp.approx.f32 %0, %1;" : "=f"(rc) : "f"(c0));

    bool  pos  = c0 > 0.0f;
    float absd = fabsf(c0 - p.K);
    float olc0 = ol * c0;
    float mn   = fminf(olc0, u2);
    float mlc  = pos ? mn : olc0;              // olc*c0
    float Bv   = (c0 + u1) - mlc;

    float s   = fmaf(c0, 0.002f, p.mthr);
    float sgp = (s > 0.0f) ? p.svm : 0.0f;
    float sg  = (s < 0.0f) ? p.nsvm : sgp;
    float C1  = fmaf(-sg, absd, Bv);
    float k1  = p.noo1 * c0;

    float qa   = u2 * absd;
    float qr   = qa * rc;
    float ola  = ol * absd;
    float oabm = fminf(ola, qr);
    float oab  = pos ? oabm : ola;             // olc*absd
    float k2   = p.oo1 * (absd - c0);
    float C2   = (Bv - absd) + oab;

    return fmaxf(fmaf(k1, r, C1), fmaf(k2, r, C2));
}

// ---------------------------------------------------------------------------
// Fused kernel: scan blocks + concurrent obsstd-reduce blocks.
// Scan: lane = chunk (L_C=32 core steps), 32 chunks per warp; span staged
// once (coalesced, swizzle o+33*(o>>5), conflict-free for staging stores,
// compute reads, and drain u2 reads). Drain packs (c0, u2) into g_cu so the
// epilogue needs a single load stream.
__global__ void __launch_bounds__(SCAN_TPB, 1)
k_main(const float2* __restrict__ x, int n, const int* __restrict__ tlp,
       const float* __restrict__ y, int ny,
       const float* pm, const float* ps,
       const float* wr_yom, const float* wr_ylm,
       const float* wr_yfm, const float* wr_yvm,
       const float* b0_yom, const float* wb1p,
       const float* b0_ylm, const float* wb2p,
       const float* b0_yrm) {
    extern __shared__ float smem[];

    if (blockIdx.x >= SCAN_BLOCKS) {
        // ---------------- obsstd reduction (fp32 accumulate) ----------------
        __shared__ double rsh[2][2];
        __shared__ int    lastf;
        int rb  = blockIdx.x - SCAN_BLOCKS;
        int tid = threadIdx.x;
        int hi = TRAINN < ny ? TRAINN : ny;
        int count = hi - SPIN;
        float s = 0.0f, s2 = 0.0f;
        for (int i = rb * SCAN_TPB + tid; i < count; i += REDB2 * SCAN_TPB) {
            float v = y[SPIN + i];
            s += v;
            s2 = fmaf(v, v, s2);
        }
        #pragma unroll
        for (int o = 16; o; o >>= 1) {
            s  += __shfl_down_sync(0xFFFFFFFFu, s,  o);
            s2 += __shfl_down_sync(0xFFFFFFFFu, s2, o);
        }
        int w = tid >> 5;
        if ((tid & 31) == 0) { rsh[w][0] = (double)s; rsh[w][1] = (double)s2; }
        __syncthreads();
        if (tid == 0) {
            g_part[2*rb]     = rsh[0][0] + rsh[1][0];
            g_part[2*rb + 1] = rsh[0][1] + rsh[1][1];
            __threadfence();
            unsigned t = atomicAdd(&g_ctr, 1u);
            lastf = (t == REDB2 - 1) ? 1 : 0;
        }
        __syncthreads();
        if (lastf) {
            double ds = 0.0, ds2 = 0.0;
            if (tid < REDB2) { ds = g_part[2*tid]; ds2 = g_part[2*tid + 1]; }
            #pragma unroll
            for (int o = 16; o; o >>= 1) {
                ds  += __shfl_down_sync(0xFFFFFFFFu, ds,  o);
                ds2 += __shfl_down_sync(0xFFFFFFFFu, ds2, o);
            }
            if ((tid & 31) == 0) { rsh[tid >> 5][0] = ds; rsh[tid >> 5][1] = ds2; }
            __syncthreads();
            if (tid == 0) {
                double ts  = rsh[0][0] + rsh[1][0];
                double ts2 = rsh[0][1] + rsh[1][1];
                double cnt = (double)count;
                float res = 0.0f;
                if (count > 1) {
                    double var = (ts2 - ts * ts / cnt) / (cnt - 1.0);
                    res = (float)sqrt(var > 0.0 ? var : 0.0);
                }
                g_obs[0] = res;
                g_ctr = 0;            // reset for next graph replay
            }
        }
        return;
    }

    // ------------------------------ scan ------------------------------
    int wid  = threadIdx.x >> 5;
    int lane = threadIdx.x & 31;
    float* su1 = smem + wid * WSTRIDE;
    float* su2 = su1 + SU_SZ;
    float* sol = su2 + SU_SZ;
    float* ssc = sol + SU_SZ;

    int tl = tlp[0];
    if (tl < 0) tl = 0;
    if (tl > n) tl = n;
    int nrem = n - tl;
    if (nrem <= 0) return;
    int nch = (nrem + L_C - 1) / L_C;

    int wch0 = (blockIdx.x * 2 + wid) * 32;   // warp's first chunk
    if (wch0 >= nch) return;

    Par p = make_par(pm, ps, wr_yom, wr_ylm, wr_yfm, wr_yvm,
                     b0_yom, wb1p, b0_ylm, wb2p, b0_yrm);

    int spanbase = tl + wch0 * L_C - WARM;

    // ---- single-shot coalesced staging + ol precompute ----
    #pragma unroll 8
    for (int o = lane; o < SPAN; o += 32) {
        int idx = spanbase + o;
        idx = idx < 0 ? 0 : (idx >= n ? n - 1 : idx);
        float2 v = x[idx];
        int so = SWZ(o);
        su1[so] = v.x;
        su2[so] = v.y;
        sol[so] = olgate(v.y, p);
    }
    __syncwarp();

    int gate_j = WARM - (wch0 + lane) * L_C;  // update admitted iff j >= gate_j
    int base_o = lane * L_C;

    float cl = 0.0f;
    int o0 = SWZ(base_o);
    float u1n = su1[o0], u2n = su2[o0], oln = sol[o0];

    // ---- warm-up (discarded; gated so chunk 0 is exact) ----
    #pragma unroll 4
    for (int j = 0; j < WARM; j++) {
        float u1 = u1n, u2 = u2n, ol = oln;
        int on = SWZ(base_o + j + 1);
        u1n = su1[on]; u2n = su2[on]; oln = sol[on];
        float cn = stepf(cl, u1, u2, ol, p);
        cl = (j >= gate_j) ? cn : cl;
    }

    // ---- core (buffers trajectory in smem) ----
    #pragma unroll 4
    for (int j = 0; j < L_C; j++) {
        ssc[lane * 33 + j] = cl;               // state ENTERING this step
        float u1 = u1n, u2 = u2n, ol = oln;
        int on = SWZ(base_o + WARM + j + 1);   // max SWZ(1072)=2161 < SU_SZ
        u1n = su1[on]; u2n = su2[on]; oln = sol[on];
        cl = stepf(cl, u1, u2, ol, p);
    }
    __syncwarp();

    // ---- coalesced drain: pack (c0, u2) ----
    #pragma unroll 4
    for (int s = 0; s < 32; s++) {
        int ch = wch0 + s;
        if (ch >= nch) break;
        int gi = tl + ch * L_C + lane;
        if (gi < n) {
            float c0 = ssc[s * 33 + lane];
            float u2 = su2[SWZ(s * L_C + WARM + lane)];
            g_cu[gi] = make_float2(c0, u2);
        }
    }
}

// ---------------------------------------------------------------------------
// Per-element gate computation for the epilogue.
__device__ __forceinline__ void gates(float c0, float u2, const Par& sp,
                                      float& h, float& ol, float& olc,
                                      float& oo, float& f, float& ov) {
    ol = olgate(u2, sp);
    float t = fmaf(c0, sp.A2, sp.B2);
    float e;  asm("ex2.approx.f32 %0, %1;" : "=f"(e) : "f"(t));
    oo = sp.oo1 / (1.0f + e);
    if (c0 > 0.0f) olc = fminf(ol, u2 / c0); else olc = ol;
    f = (1.0f - oo) - olc;
    float s = fmaf(c0, 0.002f, sp.mthr);
    float sg = (s > 0.0f) ? sp.svm : ((s < 0.0f) ? sp.nsvm : 0.0f);
    ov = fminf(sg, f);
    h = oo * c0;
}

// Vectorized epilogue (R14 4-elem shape; fed from the packed g_cu record so
// there is a single load stream: two float4 loads per 4 elements).
// Layout: [h_n | c_n | l_n | lc_n | z | z | Goo | Gol | Golc | Gf |
//          h_nout(N,2 interleaved) | obs_std | Gov]
__global__ void k_out(int n, const int* __restrict__ tlp,
                      float* __restrict__ out,
                      const float* pm, const float* ps,
                      const float* wr_yom, const float* wr_ylm,
                      const float* wr_yfm, const float* wr_yvm,
                      const float* b0_yom, const float* wb1p,
                      const float* b0_ylm, const float* wb2p,
                      const float* b0_yrm) {
    __shared__ Par sp;
    __shared__ float sobs;
    if (threadIdx.x == 0) {
        sp = make_par(pm, ps, wr_yom, wr_ylm, wr_yfm, wr_yvm,
                      b0_yom, wb1p, b0_ylm, wb2p, b0_yrm);
        sobs = g_obs[0];
    }
    __syncthreads();

    int i0 = (blockIdx.x * blockDim.x + threadIdx.x) * 4;
    if (i0 >= n) return;
    int tl = tlp[0];
    if (tl < 0) tl = 0;
    long long nn = n;
    float obss = sobs;
    bool vec = ((n & 3) == 0) && (i0 + 4 <= n);

    if (vec && (i0 + 3) < tl) {
        float4 z = make_float4(0.f, 0.f, 0.f, 0.f);
        #pragma unroll
        for (int col = 0; col < 10; col++)
            *(float4*)(out + col*nn + i0) = z;
        *(float4*)(out + 10*nn + 2*(long long)i0)     = z;
        *(float4*)(out + 10*nn + 2*(long long)i0 + 4) = z;
        *(float4*)(out + 12*nn + i0) = z;
        *(float4*)(out + 13*nn + i0) = z;
        return;
    }

    if (vec && i0 >= tl) {
        float4 r01 = *((const float4*)(g_cu + i0));      // c0_0,u2_0,c0_1,u2_1
        float4 r23 = *((const float4*)(g_cu + i0) + 1);  // c0_2,u2_2,c0_3,u2_3
        float c0a[4] = {r01.x, r01.z, r23.x, r23.z};
        float u2a[4] = {r01.y, r01.w, r23.y, r23.w};
        float h[4], ol[4], olc[4], oo[4], f[4], ov[4];
        #pragma unroll
        for (int j = 0; j < 4; j++)
            gates(c0a[j], u2a[j], sp, h[j], ol[j], olc[j], oo[j], f[j], ov[j]);

        float4 z = make_float4(0.f, 0.f, 0.f, 0.f);
        *(float4*)(out + i0)        = make_float4(h[0], h[1], h[2], h[3]);
        *(float4*)(out + nn + i0)   = make_float4(c0a[0], c0a[1], c0a[2], c0a[3]);
        *(float4*)(out + 2*nn + i0) = make_float4(ol[0]*c0a[0], ol[1]*c0a[1],
                                                  ol[2]*c0a[2], ol[3]*c0a[3]);
        *(float4*)(out + 3*nn + i0) = make_float4(olc[0]*c0a[0], olc[1]*c0a[1],
                                                  olc[2]*c0a[2], olc[3]*c0a[3]);
        *(float4*)(out + 4*nn + i0) = z;
        *(float4*)(out + 5*nn + i0) = z;
        *(float4*)(out + 6*nn + i0) = make_float4(oo[0], oo[1], oo[2], oo[3]);
        *(float4*)(out + 7*nn + i0) = make_float4(ol[0], ol[1], ol[2], ol[3]);
        *(float4*)(out + 8*nn + i0) = make_float4(olc[0], olc[1], olc[2], olc[3]);
        *(float4*)(out + 9*nn + i0) = make_float4(f[0], f[1], f[2], f[3]);
        *(float4*)(out + 10*nn + 2*(long long)i0)
            = make_float4(h[0], obss, h[1], obss);
        *(float4*)(out + 10*nn + 2*(long long)i0 + 4)
            = make_float4(h[2], obss, h[3], obss);
        *(float4*)(out + 12*nn + i0) = make_float4(obss, obss, obss, obss);
        *(float4*)(out + 13*nn + i0) = make_float4(ov[0], ov[1], ov[2], ov[3]);
        return;
    }

    // scalar fallback (straddle / tail)
    for (int j = 0; j < 4; j++) {
        int i = i0 + j;
        if (i >= n) break;
        if (i < tl) {
            out[i] = 0.0f;            out[nn + i] = 0.0f;
            out[2*nn + i] = 0.0f;     out[3*nn + i] = 0.0f;
            out[4*nn + i] = 0.0f;     out[5*nn + i] = 0.0f;
            out[6*nn + i] = 0.0f;     out[7*nn + i] = 0.0f;
            out[8*nn + i] = 0.0f;     out[9*nn + i] = 0.0f;
            out[10*nn + 2*(long long)i]     = 0.0f;
            out[10*nn + 2*(long long)i + 1] = 0.0f;
            out[12*nn + i] = 0.0f;    out[13*nn + i] = 0.0f;
            continue;
        }
        float2 cu = g_cu[i];
        float c0 = cu.x, u2 = cu.y;
        float h, ol, olc, oo, f, ov;
        gates(c0, u2, sp, h, ol, olc, oo, f, ov);
        out[i]         = h;
        out[nn + i]    = c0;
        out[2*nn + i]  = ol * c0;
        out[3*nn + i]  = olc * c0;
        out[4*nn + i]  = 0.0f;
        out[5*nn + i]  = 0.0f;
        out[6*nn + i]  = oo;
        out[7*nn + i]  = ol;
        out[8*nn + i]  = olc;
        out[9*nn + i]  = f;
        out[10*nn + 2*(long long)i]     = h;
        out[10*nn + 2*(long long)i + 1] = obss;
        out[12*nn + i] = obss;
        out[13*nn + i] = ov;
    }
}

// ---------------------------------------------------------------------------
extern "C" void kernel_launch(void* const* d_in, const int* in_sizes, int n_in,
                              void* d_out, int out_size) {
    const float2* x   = (const float2*)d_in[0];
    const float*  y   = (const float*)d_in[1];
    const float*  pm  = (const float*)d_in[2];
    const float*  ps  = (const float*)d_in[3];
    const float*  wr_yom = (const float*)d_in[4];
    const float*  wr_ylm = (const float*)d_in[5];
    const float*  wr_yfm = (const float*)d_in[6];
    const float*  wr_yvm = (const float*)d_in[7];
    const float*  b0_yom = (const float*)d_in[8];
    const float*  wb1    = (const float*)d_in[9];
    const float*  b0_ylm = (const float*)d_in[10];
    const float*  wb2    = (const float*)d_in[11];
    const float*  b0_yrm = (const float*)d_in[12];
    const int*    tlp    = (const int*)d_in[14];   // time_lag
    float* out = (float*)d_out;
    (void)n_in; (void)out_size;

    int n  = in_sizes[0] / 2;
    if (n > MAXN) n = MAXN;
    int ny = in_sizes[1];

    cudaFuncSetAttribute(k_main, cudaFuncAttributeMaxDynamicSharedMemorySize,
                         SCAN_SMEM);

    k_main<<<TOT_BLOCKS, SCAN_TPB, SCAN_SMEM>>>(x, n, tlp, y, ny,
        pm, ps, wr_yom, wr_ylm, wr_yfm, wr_yvm,
        b0_yom, wb1, b0_ylm, wb2, b0_yrm);
    int groups = (n + 3) / 4;
    k_out<<<(groups + 255) / 256, 256>>>(n, tlp, out,
        pm, ps, wr_yom, wr_ylm, wr_yfm, wr_yvm,
        b0_yom, wb1, b0_ylm, wb2, b0_yrm);
}

// round 17
// speedup vs baseline: 1.3830x; 1.3830x over previous
#include <cuda_runtime.h>
#include <math.h>

// Problem constants (from reference)
#define MAXN   524288
#define SPIN   1000
#define TRAINN 400000
#define ML_C   2.9086f
#define SL_C   1.898f

#define L_C    32                 // core steps per chunk (lane)
#define WARM   48                 // speculative burn-in (bit-identical at 48)
#define STEPS  (WARM + L_C)       // 80 sequential steps per lane
#define SPAN   (31*L_C + STEPS)   // 1072 unique elements per warp
#define SU_SZ  2168               // >= SWZ(SPAN)=2161 (+pad)
#define SWZ(o) ((o) + 33*((o) >> 5))
#define SSC_SZ (32*33)
#define WSTRIDE (3*SU_SZ + SSC_SZ)
#define SCAN_TPB 64
#define SCAN_BLOCKS 256
#define REDB2   128               // reduce+fill blocks appended to the grid
#define TOT_BLOCKS (SCAN_BLOCKS + REDB2)   // 384 <= 444 co-resident slots
#define SCAN_SMEM (2*WSTRIDE*4)   // bytes (2 warps)

// Scratch (no allocations allowed)
__device__ float    g_c[MAXN];        // state entering each step
__device__ double   g_part[REDB2*2];  // per-block partial sums
__device__ unsigned g_ctr  = 0;       // reduce completion counter (self-reset)
__device__ unsigned g_flag = 0;       // obsstd-ready flag (self-reset)
__device__ unsigned g_done = 0;       // fill completion counter (self-reset)
__device__ float    g_obs[1];         // obsstd result

// ---------------------------------------------------------------------------
struct Par {
    float A2, B2, oo1, noo1, svm, nsvm, mthr, K, AL, BL, ol1;
};

__device__ __forceinline__ Par make_par(
        const float* pm, const float* ps,
        const float* wr_yom, const float* wr_ylm,
        const float* wr_yfm, const float* wr_yvm,
        const float* b0_yom, const float* wb1p,
        const float* b0_ylm, const float* wb2p,
        const float* b0_yrm) {
    const float LOG2E = 1.4426950408889634f;
    Par p;
    float eo = expf(wr_yom[0]);
    float el = expf(wr_ylm[0]);
    float ef = expf(wr_yfm[0]);
    float den = eo + el + ef;
    p.oo1  = eo / den;
    p.ol1  = el / den;
    p.noo1 = -p.oo1;
    p.svm  = 1.0f / (1.0f + expf(-wr_yvm[0]));
    p.nsvm = -p.svm;
    float thr = expf(b0_yrm[0]);
    p.mthr = -thr;
    p.K    = thr * 500.0f;
    float a = wb1p[0] / ps[0];
    p.A2 = -LOG2E * a;
    p.B2 = -LOG2E * (b0_yom[0] - pm[0] * a);
    float al = wb2p[0] / SL_C;
    p.AL = -LOG2E * al;
    p.BL = -LOG2E * (b0_ylm[0] - ML_C * al);
    return p;
}

__device__ __forceinline__ float olgate(float u2, const Par& p) {
    float t = fmaf(u2, p.AL, p.BL);
    float e; asm("ex2.approx.f32 %0, %1;" : "=f"(e) : "f"(t));
    float r; asm("rcp.approx.f32 %0, %1;" : "=f"(r) : "f"(1.0f + e));
    return p.ol1 * r;
}

// One recurrence step (branch-free; all selects are FSELs). ol precomputed.
__device__ __forceinline__ float stepf(float c0, float u1, float u2, float ol,
                                       const Par& p) {
    float t = fmaf(c0, p.A2, p.B2);
    float e;  asm("ex2.approx.f32 %0, %1;" : "=f"(e) : "f"(t));
    float d = 1.0f + e;
    float r;  asm("rcp.approx.f32 %0, %1;" : "=f"(r) : "f"(d));
    float rc; asm("rcp.approx.f32 %0, %1;" : "=f"(rc) : "f"(c0));

    bool  pos  = c0 > 0.0f;
    float absd = fabsf(c0 - p.K);
    float olc0 = ol * c0;
    float mn   = fminf(olc0, u2);
    float mlc  = pos ? mn : olc0;              // olc*c0
    float Bv   = (c0 + u1) - mlc;

    float s   = fmaf(c0, 0.002f, p.mthr);
    float sgp = (s > 0.0f) ? p.svm : 0.0f;
    float sg  = (s < 0.0f) ? p.nsvm : sgp;
    float C1  = fmaf(-sg, absd, Bv);
    float k1  = p.noo1 * c0;

    float qa   = u2 * absd;
    float qr   = qa * rc;
    float ola  = ol * absd;
    float oabm = fminf(ola, qr);
    float oab  = pos ? oabm : ola;             // olc*absd
    float k2   = p.oo1 * (absd - c0);
    float C2   = (Bv - absd) + oab;

    return fmaxf(fmaf(k1, r, C1), fmaf(k2, r, C2));
}

// ---------------------------------------------------------------------------
// Fused kernel.
// Blocks [0, SCAN_BLOCKS): warp-SIMD speculative chunk scan (R14 form).
// Blocks [SCAN_BLOCKS, TOT_BLOCKS): fp32 obsstd reduction, then — while the
// scan blocks are still running — fill the scan-independent output columns:
// cols 4,5 (zeros) immediately, col 12 (obsstd) after a co-resident
// flag-spin on the publisher. All 384 blocks fit in one wave (60.5KB smem ->
// 3 blocks/SM -> 444 slots), so the spin cannot deadlock; counters
// self-reset for graph replay.
__global__ void __launch_bounds__(SCAN_TPB, 1)
k_main(const float2* __restrict__ x, int n, const int* __restrict__ tlp,
       float* __restrict__ out,
       const float* __restrict__ y, int ny,
       const float* pm, const float* ps,
       const float* wr_yom, const float* wr_ylm,
       const float* wr_yfm, const float* wr_yvm,
       const float* b0_yom, const float* wb1p,
       const float* b0_ylm, const float* wb2p,
       const float* b0_yrm) {
    extern __shared__ float smem[];
    long long nn = n;

    if (blockIdx.x >= SCAN_BLOCKS) {
        // ---------------- obsstd reduction (fp32 accumulate) ----------------
        __shared__ double rsh[2][2];
        __shared__ int    lastf;
        int rb  = blockIdx.x - SCAN_BLOCKS;
        int tid = threadIdx.x;
        int hi = TRAINN < ny ? TRAINN : ny;
        int count = hi - SPIN;
        float s = 0.0f, s2 = 0.0f;
        for (int i = rb * SCAN_TPB + tid; i < count; i += REDB2 * SCAN_TPB) {
            float v = y[SPIN + i];
            s += v;
            s2 = fmaf(v, v, s2);
        }
        #pragma unroll
        for (int o = 16; o; o >>= 1) {
            s  += __shfl_down_sync(0xFFFFFFFFu, s,  o);
            s2 += __shfl_down_sync(0xFFFFFFFFu, s2, o);
        }
        int w = tid >> 5;
        if ((tid & 31) == 0) { rsh[w][0] = (double)s; rsh[w][1] = (double)s2; }
        __syncthreads();
        if (tid == 0) {
            g_part[2*rb]     = rsh[0][0] + rsh[1][0];
            g_part[2*rb + 1] = rsh[0][1] + rsh[1][1];
            __threadfence();
            unsigned t = atomicAdd(&g_ctr, 1u);
            lastf = (t == REDB2 - 1) ? 1 : 0;
        }
        __syncthreads();
        if (lastf) {
            // parallel combine of 128 partials (2 per thread over 64 threads)
            double ds  = g_part[2*tid]       + g_part[2*tid + 128];
            double ds2 = g_part[2*tid + 1]   + g_part[2*tid + 129];
            #pragma unroll
            for (int o = 16; o; o >>= 1) {
                ds  += __shfl_down_sync(0xFFFFFFFFu, ds,  o);
                ds2 += __shfl_down_sync(0xFFFFFFFFu, ds2, o);
            }
            if ((tid & 31) == 0) { rsh[tid >> 5][0] = ds; rsh[tid >> 5][1] = ds2; }
            __syncthreads();
            if (tid == 0) {
                double ts  = rsh[0][0] + rsh[1][0];
                double ts2 = rsh[0][1] + rsh[1][1];
                double cnt = (double)count;
                float res = 0.0f;
                if (count > 1) {
                    double var = (ts2 - ts * ts / cnt) / (cnt - 1.0);
                    res = (float)sqrt(var > 0.0 ? var : 0.0);
                }
                g_obs[0] = res;
                g_ctr = 0;                    // reset for next graph replay
                __threadfence();
                atomicExch(&g_flag, 1u);      // publish obsstd
            }
        }

        // ---- fill cols 4,5 (zeros; no dependency on scan or obsstd) ----
        int tl = tlp[0];
        if (tl < 0) tl = 0;
        if (tl > n) tl = n;
        int tid0   = rb * SCAN_TPB + threadIdx.x;
        int stride = REDB2 * SCAN_TPB;
        if ((n & 3) == 0) {
            int n4 = n >> 2;
            float4 z = make_float4(0.f, 0.f, 0.f, 0.f);
            for (int q = tid0; q < n4; q += stride) {
                ((float4*)(out + 4*nn))[q] = z;
                ((float4*)(out + 5*nn))[q] = z;
            }
        } else {
            for (int i = tid0; i < n; i += stride) {
                out[4*nn + i] = 0.0f;
                out[5*nn + i] = 0.0f;
            }
        }

        // ---- wait for obsstd, then fill col 12 ----
        if (threadIdx.x == 0) {
            while (atomicAdd(&g_flag, 0u) == 0u) { }
        }
        __syncthreads();
        float ob = *((volatile float*)g_obs);
        if ((n & 3) == 0) {
            int n4 = n >> 2;
            for (int q = tid0; q < n4; q += stride) {
                int i0 = q << 2;
                float4 v;
                if (i0 + 3 < tl)      v = make_float4(0.f, 0.f, 0.f, 0.f);
                else if (i0 >= tl)    v = make_float4(ob, ob, ob, ob);
                else {
                    v.x = (i0     < tl) ? 0.f : ob;
                    v.y = (i0 + 1 < tl) ? 0.f : ob;
                    v.z = (i0 + 2 < tl) ? 0.f : ob;
                    v.w = (i0 + 3 < tl) ? 0.f : ob;
                }
                ((float4*)(out + 12*nn))[q] = v;
            }
        } else {
            for (int i = tid0; i < n; i += stride)
                out[12*nn + i] = (i < tl) ? 0.0f : ob;
        }

        // ---- last fill block resets the flag for graph replay ----
        if (threadIdx.x == 0) {
            __threadfence();
            unsigned t = atomicAdd(&g_done, 1u);
            if (t == REDB2 - 1u) {
                g_done = 0u;
                atomicExch(&g_flag, 0u);
            }
        }
        return;
    }

    // ------------------------------ scan ------------------------------
    int wid  = threadIdx.x >> 5;
    int lane = threadIdx.x & 31;
    float* su1 = smem + wid * WSTRIDE;
    float* su2 = su1 + SU_SZ;
    float* sol = su2 + SU_SZ;
    float* ssc = sol + SU_SZ;

    int tl = tlp[0];
    if (tl < 0) tl = 0;
    if (tl > n) tl = n;
    int nrem = n - tl;
    if (nrem <= 0) return;
    int nch = (nrem + L_C - 1) / L_C;

    int wch0 = (blockIdx.x * 2 + wid) * 32;   // warp's first chunk
    if (wch0 >= nch) return;

    Par p = make_par(pm, ps, wr_yom, wr_ylm, wr_yfm, wr_yvm,
                     b0_yom, wb1p, b0_ylm, wb2p, b0_yrm);

    int spanbase = tl + wch0 * L_C - WARM;

    // ---- single-shot coalesced staging + ol precompute ----
    #pragma unroll 8
    for (int o = lane; o < SPAN; o += 32) {
        int idx = spanbase + o;
        idx = idx < 0 ? 0 : (idx >= n ? n - 1 : idx);
        float2 v = x[idx];
        int so = SWZ(o);
        su1[so] = v.x;
        su2[so] = v.y;
        sol[so] = olgate(v.y, p);
    }
    __syncwarp();

    int gate_j = WARM - (wch0 + lane) * L_C;  // update admitted iff j >= gate_j
    int base_o = lane * L_C;

    float cl = 0.0f;
    int o0 = SWZ(base_o);
    float u1n = su1[o0], u2n = su2[o0], oln = sol[o0];

    // ---- warm-up (discarded; gated so chunk 0 is exact) ----
    #pragma unroll 4
    for (int j = 0; j < WARM; j++) {
        float u1 = u1n, u2 = u2n, ol = oln;
        int on = SWZ(base_o + j + 1);
        u1n = su1[on]; u2n = su2[on]; oln = sol[on];
        float cn = stepf(cl, u1, u2, ol, p);
        cl = (j >= gate_j) ? cn : cl;
    }

    // ---- core (buffers trajectory in smem) ----
    #pragma unroll 4
    for (int j = 0; j < L_C; j++) {
        ssc[lane * 33 + j] = cl;               // state ENTERING this step
        float u1 = u1n, u2 = u2n, ol = oln;
        int on = SWZ(base_o + WARM + j + 1);   // max SWZ(1072)=2161 < SU_SZ
        u1n = su1[on]; u2n = su2[on]; oln = sol[on];
        cl = stepf(cl, u1, u2, ol, p);
    }
    __syncwarp();

    // ---- coalesced drain ----
    #pragma unroll 4
    for (int s = 0; s < 32; s++) {
        int ch = wch0 + s;
        if (ch >= nch) break;
        int gi = tl + ch * L_C + lane;
        if (gi < n) g_c[gi] = ssc[s * 33 + lane];
    }
}

// ---------------------------------------------------------------------------
// Per-element gate computation for the epilogue.
__device__ __forceinline__ void gates(float c0, float u2, const Par& sp,
                                      float& h, float& ol, float& olc,
                                      float& oo, float& f, float& ov) {
    ol = olgate(u2, sp);
    float t = fmaf(c0, sp.A2, sp.B2);
    float e;  asm("ex2.approx.f32 %0, %1;" : "=f"(e) : "f"(t));
    oo = sp.oo1 / (1.0f + e);
    if (c0 > 0.0f) olc = fminf(ol, u2 / c0); else olc = ol;
    f = (1.0f - oo) - olc;
    float s = fmaf(c0, 0.002f, sp.mthr);
    float sg = (s > 0.0f) ? sp.svm : ((s < 0.0f) ? sp.nsvm : 0.0f);
    ov = fminf(sg, f);
    h = oo * c0;
}

// Vectorized epilogue (R14 4-elem shape — measured best). Writes 11 of 14
// columns; cols 4,5,12 are filled concurrently by k_main's reduce blocks.
// Layout: [h_n | c_n | l_n | lc_n | z | z | Goo | Gol | Golc | Gf |
//          h_nout(N,2 interleaved) | obs_std | Gov]
__global__ void k_out(const float2* __restrict__ x, int n,
                      const int* __restrict__ tlp, float* __restrict__ out,
                      const float* pm, const float* ps,
                      const float* wr_yom, const float* wr_ylm,
                      const float* wr_yfm, const float* wr_yvm,
                      const float* b0_yom, const float* wb1p,
                      const float* b0_ylm, const float* wb2p,
                      const float* b0_yrm) {
    __shared__ Par sp;
    __shared__ float sobs;
    if (threadIdx.x == 0) {
        sp = make_par(pm, ps, wr_yom, wr_ylm, wr_yfm, wr_yvm,
                      b0_yom, wb1p, b0_ylm, wb2p, b0_yrm);
        sobs = g_obs[0];
    }
    __syncthreads();

    int i0 = (blockIdx.x * blockDim.x + threadIdx.x) * 4;
    if (i0 >= n) return;
    int tl = tlp[0];
    if (tl < 0) tl = 0;
    long long nn = n;
    float obss = sobs;
    bool vec = ((n & 3) == 0) && (i0 + 4 <= n);

    if (vec && (i0 + 3) < tl) {
        float4 z = make_float4(0.f, 0.f, 0.f, 0.f);
        *(float4*)(out + i0)        = z;
        *(float4*)(out + nn + i0)   = z;
        *(float4*)(out + 2*nn + i0) = z;
        *(float4*)(out + 3*nn + i0) = z;
        *(float4*)(out + 6*nn + i0) = z;
        *(float4*)(out + 7*nn + i0) = z;
        *(float4*)(out + 8*nn + i0) = z;
        *(float4*)(out + 9*nn + i0) = z;
        *(float4*)(out + 10*nn + 2*(long long)i0)     = z;
        *(float4*)(out + 10*nn + 2*(long long)i0 + 4) = z;
        *(float4*)(out + 13*nn + i0) = z;
        return;
    }

    if (vec && i0 >= tl) {
        float4 c4  = *(const float4*)(g_c + i0);
        float4 x01 = __ldg((const float4*)(x + i0));
        float4 x23 = __ldg((const float4*)(x + i0) + 1);
        float c0a[4] = {c4.x, c4.y, c4.z, c4.w};
        float u2a[4] = {x01.y, x01.w, x23.y, x23.w};
        float h[4], ol[4], olc[4], oo[4], f[4], ov[4];
        #pragma unroll
        for (int j = 0; j < 4; j++)
            gates(c0a[j], u2a[j], sp, h[j], ol[j], olc[j], oo[j], f[j], ov[j]);

        *(float4*)(out + i0)        = make_float4(h[0], h[1], h[2], h[3]);
        *(float4*)(out + nn + i0)   = c4;
        *(float4*)(out + 2*nn + i0) = make_float4(ol[0]*c0a[0], ol[1]*c0a[1],
                                                  ol[2]*c0a[2], ol[3]*c0a[3]);
        *(float4*)(out + 3*nn + i0) = make_float4(olc[0]*c0a[0], olc[1]*c0a[1],
                                                  olc[2]*c0a[2], olc[3]*c0a[3]);
        *(float4*)(out + 6*nn + i0) = make_float4(oo[0], oo[1], oo[2], oo[3]);
        *(float4*)(out + 7*nn + i0) = make_float4(ol[0], ol[1], ol[2], ol[3]);
        *(float4*)(out + 8*nn + i0) = make_float4(olc[0], olc[1], olc[2], olc[3]);
        *(float4*)(out + 9*nn + i0) = make_float4(f[0], f[1], f[2], f[3]);
        *(float4*)(out + 10*nn + 2*(long long)i0)
            = make_float4(h[0], obss, h[1], obss);
        *(float4*)(out + 10*nn + 2*(long long)i0 + 4)
            = make_float4(h[2], obss, h[3], obss);
        *(float4*)(out + 13*nn + i0) = make_float4(ov[0], ov[1], ov[2], ov[3]);
        return;
    }

    // scalar fallback (straddle / tail)
    for (int j = 0; j < 4; j++) {
        int i = i0 + j;
        if (i >= n) break;
        if (i < tl) {
            out[i] = 0.0f;            out[nn + i] = 0.0f;
            out[2*nn + i] = 0.0f;     out[3*nn + i] = 0.0f;
            out[6*nn + i] = 0.0f;     out[7*nn + i] = 0.0f;
            out[8*nn + i] = 0.0f;     out[9*nn + i] = 0.0f;
            out[10*nn + 2*(long long)i]     = 0.0f;
            out[10*nn + 2*(long long)i + 1] = 0.0f;
            out[13*nn + i] = 0.0f;
            continue;
        }
        float c0 = g_c[i];
        float u2 = x[i].y;
        float h, ol, olc, oo, f, ov;
        gates(c0, u2, sp, h, ol, olc, oo, f, ov);
        out[i]         = h;
        out[nn + i]    = c0;
        out[2*nn + i]  = ol * c0;
        out[3*nn + i]  = olc * c0;
        out[6*nn + i]  = oo;
        out[7*nn + i]  = ol;
        out[8*nn + i]  = olc;
        out[9*nn + i]  = f;
        out[10*nn + 2*(long long)i]     = h;
        out[10*nn + 2*(long long)i + 1] = obss;
        out[13*nn + i] = ov;
    }
}

// ---------------------------------------------------------------------------
extern "C" void kernel_launch(void* const* d_in, const int* in_sizes, int n_in,
                              void* d_out, int out_size) {
    const float2* x   = (const float2*)d_in[0];
    const float*  y   = (const float*)d_in[1];
    const float*  pm  = (const float*)d_in[2];
    const float*  ps  = (const float*)d_in[3];
    const float*  wr_yom = (const float*)d_in[4];
    const float*  wr_ylm = (const float*)d_in[5];
    const float*  wr_yfm = (const float*)d_in[6];
    const float*  wr_yvm = (const float*)d_in[7];
    const float*  b0_yom = (const float*)d_in[8];
    const float*  wb1    = (const float*)d_in[9];
    const float*  b0_ylm = (const float*)d_in[10];
    const float*  wb2    = (const float*)d_in[11];
    const float*  b0_yrm = (const float*)d_in[12];
    const int*    tlp    = (const int*)d_in[14];   // time_lag
    float* out = (float*)d_out;
    (void)n_in; (void)out_size;

    int n  = in_sizes[0] / 2;
    if (n > MAXN) n = MAXN;
    int ny = in_sizes[1];

    cudaFuncSetAttribute(k_main, cudaFuncAttributeMaxDynamicSharedMemorySize,
                         SCAN_SMEM);

    k_main<<<TOT_BLOCKS, SCAN_TPB, SCAN_SMEM>>>(x, n, tlp, out, y, ny,
        pm, ps, wr_yom, wr_ylm, wr_yfm, wr_yvm,
        b0_yom, wb1, b0_ylm, wb2, b0_yrm);
    int groups = (n + 3) / 4;
    k_out<<<(groups + 255) / 256, 256>>>(x, n, tlp, out,
        pm, ps, wr_yom, wr_ylm, wr_yfm, wr_yvm,
        b0_yom, wb1, b0_ylm, wb2, b0_yrm);
}